// round 3
// baseline (speedup 1.0000x reference)
#include <cuda_runtime.h>
#include <cuda_fp16.h>
#include <cstdint>

// ============================================================================
// logits = x[2048,512] @ fq[65536,512]^T ; per-row argmax/argmin;
// out = [rep[argmax] (2048x512) | rep[argmin] (2048x512)] fp32.
//
// Plan (sm_100 baseline ISA only — no tcgen05 on this toolchain):
//   1) convert x, fq to fp16
//   2) fp16 mma.sync GEMM + fused per-row max/min + candidate collection
//      (threshold = best-so-far - margin; superset of true arg-extrema)
//   3) exact fp64-accum rescore of candidates + gather rep rows
// ============================================================================

#define B_ROWS 2048
#define K_ENT  65536
#define F_DIM  512

#define BM 128
#define BN 128
#define BK 32
#define NCH    (F_DIM / BK)       // 16
#define N_KTILES (K_ENT / BN)     // 512
#define N_RTILES (B_ROWS / BM)    // 16

#define STAGES  3
#define PITCH   80                 // 64B data + 16B pad (conflict-free ldmatrix)
#define A_BYTES (BM * PITCH)       // 10240
#define STAGE_B (2 * BM * PITCH)   // 20480 (A then B)
#define SMEM_TOTAL (STAGES * STAGE_B)  // 61440

#define MARGIN 0.15f
#define CAP    512

// ---------------------------------------------------------------------------
// Static device scratch
// ---------------------------------------------------------------------------
__device__ __half   g_fqh[(size_t)K_ENT * F_DIM];     // 64 MB
__device__ __half   g_xh [(size_t)B_ROWS * F_DIM];    // 2 MB
__device__ uint32_t g_mkey[2][B_ROWS];                // [0]=fkey(max), [1]=~fkey(min)
__device__ uint32_t g_ccnt[2][B_ROWS];
__device__ uint32_t g_cand[2][B_ROWS][CAP];           // 8 MB

// ---------------------------------------------------------------------------
// Helpers
// ---------------------------------------------------------------------------
__device__ __forceinline__ uint32_t smem_u32(const void* p) {
    uint32_t a;
    asm("{ .reg .u64 t; cvta.to.shared.u64 t, %1; cvt.u32.u64 %0, t; }"
        : "=r"(a) : "l"(p));
    return a;
}
__device__ __forceinline__ uint32_t fkey(float v) {
    uint32_t u = __float_as_uint(v);
    return (u & 0x80000000u) ? ~u : (u | 0x80000000u);
}
__device__ __forceinline__ float unfkey(uint32_t k) {
    uint32_t u = (k & 0x80000000u) ? (k & 0x7FFFFFFFu) : ~k;
    return __uint_as_float(u);
}
__device__ __forceinline__ void cp_async16(uint32_t sd, const void* g) {
    asm volatile("cp.async.cg.shared.global [%0], [%1], 16;"
                 :: "r"(sd), "l"(g) : "memory");
}
__device__ __forceinline__ void cp_commit() {
    asm volatile("cp.async.commit_group;" ::: "memory");
}
__device__ __forceinline__ void ldm_x4(uint32_t* r, uint32_t addr) {
    asm volatile("ldmatrix.sync.aligned.m8n8.x4.shared.b16 {%0,%1,%2,%3}, [%4];"
                 : "=r"(r[0]), "=r"(r[1]), "=r"(r[2]), "=r"(r[3]) : "r"(addr));
}
__device__ __forceinline__ void mma16816(float* c, const uint32_t* a,
                                         uint32_t b0, uint32_t b1) {
    asm volatile(
        "mma.sync.aligned.m16n8k16.row.col.f32.f16.f16.f32 "
        "{%0,%1,%2,%3}, {%4,%5,%6,%7}, {%8,%9}, {%0,%1,%2,%3};"
        : "+f"(c[0]), "+f"(c[1]), "+f"(c[2]), "+f"(c[3])
        : "r"(a[0]), "r"(a[1]), "r"(a[2]), "r"(a[3]), "r"(b0), "r"(b1));
}

// ---------------------------------------------------------------------------
// Kernel 1: fp32 -> fp16 conversion
// ---------------------------------------------------------------------------
__device__ __forceinline__ void conv4(__half* dst, const float4* __restrict__ src, int i) {
    float4 v = src[i];
    __half2* d = reinterpret_cast<__half2*>(dst);
    d[2 * (size_t)i]     = __floats2half2_rn(v.x, v.y);
    d[2 * (size_t)i + 1] = __floats2half2_rn(v.z, v.w);
}
__global__ void convert_fq_kernel(const float4* __restrict__ src, int n4) {
    int i = blockIdx.x * blockDim.x + threadIdx.x;
    if (i < n4) conv4(g_fqh, src, i);
}
__global__ void convert_x_kernel(const float4* __restrict__ src, int n4) {
    int i = blockIdx.x * blockDim.x + threadIdx.x;
    if (i < n4) conv4(g_xh, src, i);
}

// ---------------------------------------------------------------------------
// Kernel 2: reset state (deterministic across graph replays)
// ---------------------------------------------------------------------------
__global__ void init_kernel() {
    int i = blockIdx.x * blockDim.x + threadIdx.x;
    if (i < B_ROWS) {
        g_mkey[0][i] = 0u; g_mkey[1][i] = 0u;
        g_ccnt[0][i] = 0u; g_ccnt[1][i] = 0u;
    }
}

// ---------------------------------------------------------------------------
// Kernel 3: fp16 GEMM (mma.sync) + fused max/min + candidate collection
// ---------------------------------------------------------------------------
__device__ __forceinline__ void load_chunk(uint32_t sb, int stage, int c,
                                           int rowbase, int nbase, int tid) {
    const uint32_t st = sb + (uint32_t)stage * STAGE_B;
    #pragma unroll
    for (int i = 0; i < 2; i++) {            // A: 128 rows x 32 f16 (4 x 16B / row)
        const int u = tid + i * 256;
        const int row = u >> 2, c16 = u & 3;
        cp_async16(st + row * PITCH + c16 * 16,
                   g_xh + (size_t)(rowbase + row) * F_DIM + c * BK + c16 * 8);
    }
    #pragma unroll
    for (int i = 0; i < 2; i++) {            // B: 128 n-rows x 32 f16
        const int u = tid + i * 256;
        const int row = u >> 2, c16 = u & 3;
        cp_async16(st + A_BYTES + row * PITCH + c16 * 16,
                   g_fqh + (size_t)(nbase + row) * F_DIM + c * BK + c16 * 8);
    }
    cp_commit();
}

__global__ void __launch_bounds__(256) gemm_argext_kernel() {
    extern __shared__ char smem[];
    const uint32_t sb = smem_u32(smem);
    const int tid  = threadIdx.x;
    const int lane = tid & 31;
    const int wid  = tid >> 5;
    const int wm   = wid >> 2;               // 0..1 (M)
    const int wn   = wid & 3;                // 0..3 (N)

    const int bid     = blockIdx.x;
    const int ktile   = bid >> 4;            // consecutive bids share fq slab (L2)
    const int rowtile = bid & 15;
    const int rowbase = rowtile * BM;
    const int nbase   = ktile * BN;

    float acc[4][4][4];
    #pragma unroll
    for (int a = 0; a < 4; a++)
        #pragma unroll
        for (int b = 0; b < 4; b++)
            #pragma unroll
            for (int d = 0; d < 4; d++) acc[a][b][d] = 0.0f;

    load_chunk(sb, 0, 0, rowbase, nbase, tid);
    load_chunk(sb, 1, 1, rowbase, nbase, tid);

    const int lr = lane & 15;
    const int lc = lane >> 4;

    for (int c = 0; c < NCH; c++) {
        asm volatile("cp.async.wait_group 1;" ::: "memory");
        __syncthreads();
        if (c + 2 < NCH) load_chunk(sb, (c + 2) % STAGES, c + 2, rowbase, nbase, tid);
        else             cp_commit();        // empty group keeps wait math uniform

        const uint32_t a_base = sb + (uint32_t)(c % STAGES) * STAGE_B;
        const uint32_t b_base = a_base + A_BYTES;

        #pragma unroll
        for (int k16 = 0; k16 < 2; k16++) {
            uint32_t af[4][4], bf[2][4];
            #pragma unroll
            for (int mi = 0; mi < 4; mi++)
                ldm_x4(af[mi], a_base + (64 * wm + 16 * mi + lr) * PITCH
                               + lc * 16 + k16 * 32);
            #pragma unroll
            for (int nb = 0; nb < 2; nb++)
                ldm_x4(bf[nb], b_base + (32 * wn + 16 * nb + lr) * PITCH
                               + lc * 16 + k16 * 32);
            #pragma unroll
            for (int mi = 0; mi < 4; mi++)
                #pragma unroll
                for (int ni = 0; ni < 4; ni++) {
                    const int nb = ni >> 1, s = ni & 1;
                    mma16816(acc[mi][ni], af[mi], bf[nb][s], bf[nb][s + 2]);
                }
        }
    }

    // ---------------- epilogue: per-row max/min + candidates ----------------
    __syncthreads();                          // all async/smem use done; overlay
    uint32_t* s_maxkey = reinterpret_cast<uint32_t*>(smem);          // [128]
    uint32_t* s_minkey = s_maxkey + 128;                             // [128]
    float*    s_thr    = reinterpret_cast<float*>(s_minkey + 128);   // [256]

    if (tid < 128) { s_maxkey[tid] = 0u; s_minkey[tid] = 0u; }
    __syncthreads();

    #pragma unroll
    for (int mi = 0; mi < 4; mi++) {
        #pragma unroll
        for (int h = 0; h < 2; h++) {
            float vmax = -3.402823466e38f, vmin = 3.402823466e38f;
            #pragma unroll
            for (int ni = 0; ni < 4; ni++)
                #pragma unroll
                for (int j = 0; j < 2; j++) {
                    const float v = acc[mi][ni][2 * h + j];
                    vmax = fmaxf(vmax, v);
                    vmin = fminf(vmin, v);
                }
            #pragma unroll
            for (int off = 1; off < 4; off <<= 1) {
                vmax = fmaxf(vmax, __shfl_xor_sync(0xFFFFFFFFu, vmax, off));
                vmin = fminf(vmin, __shfl_xor_sync(0xFFFFFFFFu, vmin, off));
            }
            if ((lane & 3) == 0) {
                const int r = 64 * wm + 16 * mi + (lane >> 2) + 8 * h;
                atomicMax(&s_maxkey[r], fkey(vmax));
                atomicMax(&s_minkey[r], ~fkey(vmin));
            }
        }
    }
    __syncthreads();

    if (tid < 128) {
        const int rg = rowbase + tid;
        const float tmax = unfkey(s_maxkey[tid]);
        const uint32_t oldmax = atomicMax(&g_mkey[0][rg], s_maxkey[tid]);
        s_thr[tid] = fmaxf(unfkey(oldmax), tmax) - MARGIN;

        const float tmin = unfkey(~s_minkey[tid]);
        const uint32_t oldmin = atomicMax(&g_mkey[1][rg], s_minkey[tid]);
        s_thr[128 + tid] = fminf(unfkey(~oldmin), tmin) + MARGIN;
    }
    __syncthreads();

    #pragma unroll
    for (int mi = 0; mi < 4; mi++) {
        #pragma unroll
        for (int h = 0; h < 2; h++) {
            const int rl = 64 * wm + 16 * mi + (lane >> 2) + 8 * h;
            const float thrmax = s_thr[rl];
            const float thrmin = s_thr[128 + rl];
            const int rg = rowbase + rl;
            #pragma unroll
            for (int ni = 0; ni < 4; ni++)
                #pragma unroll
                for (int j = 0; j < 2; j++) {
                    const float v = acc[mi][ni][2 * h + j];
                    if (v >= thrmax || v <= thrmin) {
                        const uint32_t col = nbase + 32 * wn + 16 * (ni >> 1)
                                           + 8 * (ni & 1) + 2 * (lane & 3) + j;
                        if (v >= thrmax) {
                            const uint32_t p = atomicAdd(&g_ccnt[0][rg], 1u);
                            if (p < CAP) g_cand[0][rg][p] = col;
                        }
                        if (v <= thrmin) {
                            const uint32_t p = atomicAdd(&g_ccnt[1][rg], 1u);
                            if (p < CAP) g_cand[1][rg][p] = col;
                        }
                    }
                }
        }
    }
}

// ---------------------------------------------------------------------------
// Kernel 4: exact rescore (fp64 accum) + gather
// ---------------------------------------------------------------------------
__global__ void __launch_bounds__(256) rescore_kernel(
    const float* __restrict__ x, const float* __restrict__ fq,
    const float* __restrict__ rep, float* __restrict__ out) {
    const int row  = blockIdx.x;
    const int side = blockIdx.y;            // 0 = max(pos), 1 = min(neg)
    const int tid  = threadIdx.x;

    __shared__ float  sx[F_DIM];
    __shared__ double red[8];
    __shared__ uint32_t s_bidx;

    #pragma unroll
    for (int i = tid; i < F_DIM; i += 256) sx[i] = x[(size_t)row * F_DIM + i];
    __syncthreads();

    uint32_t cnt = g_ccnt[side][row];
    if (cnt > CAP) cnt = CAP;

    double  bestv = side ? 1.0e300 : -1.0e300;
    uint32_t bidx = 0xFFFFFFFFu;

    for (uint32_t i = 0; i < cnt; i++) {
        const uint32_t idx = g_cand[side][row][i];
        const float* fr = fq + (size_t)idx * F_DIM;
        double p = 0.0;
        #pragma unroll
        for (int j = tid; j < F_DIM; j += 256)
            p += (double)sx[j] * (double)fr[j];
        #pragma unroll
        for (int off = 16; off > 0; off >>= 1)
            p += __shfl_xor_sync(0xFFFFFFFFu, p, off);
        if ((tid & 31) == 0) red[tid >> 5] = p;
        __syncthreads();
        if (tid == 0) {
            double d = 0.0;
            #pragma unroll
            for (int w = 0; w < 8; w++) d += red[w];
            const bool better = side ? (d < bestv || (d == bestv && idx < bidx))
                                     : (d > bestv || (d == bestv && idx < bidx));
            if (better) { bestv = d; bidx = idx; }
        }
        __syncthreads();
    }
    if (tid == 0) s_bidx = bidx;
    __syncthreads();

    const float2* src = reinterpret_cast<const float2*>(rep + (size_t)s_bidx * F_DIM);
    float2* dst = reinterpret_cast<float2*>(
        out + (size_t)side * B_ROWS * F_DIM + (size_t)row * F_DIM);
    dst[tid] = src[tid];                    // 256 threads x 8B = 512 floats
}

// ---------------------------------------------------------------------------
// Entry point
// ---------------------------------------------------------------------------
extern "C" void kernel_launch(void* const* d_in, const int* in_sizes, int n_in,
                              void* d_out, int out_size) {
    const float* x   = (const float*)d_in[0];  // [2048, 512]
    const float* fq  = (const float*)d_in[1];  // [65536, 512]
    const float* rep = (const float*)d_in[2];  // [65536, 512]
    float* out = (float*)d_out;                // [2, 2048, 512]

    cudaFuncSetAttribute(gemm_argext_kernel,
                         cudaFuncAttributeMaxDynamicSharedMemorySize, SMEM_TOTAL);

    {
        const int n4 = (K_ENT * F_DIM) / 4;
        convert_fq_kernel<<<n4 / 256, 256>>>(reinterpret_cast<const float4*>(fq), n4);
    }
    {
        const int n4 = (B_ROWS * F_DIM) / 4;
        convert_x_kernel<<<n4 / 256, 256>>>(reinterpret_cast<const float4*>(x), n4);
    }
    init_kernel<<<(B_ROWS + 255) / 256, 256>>>();

    gemm_argext_kernel<<<N_KTILES * N_RTILES, 256, SMEM_TOTAL>>>();

    dim3 rgrid(B_ROWS, 2);
    rescore_kernel<<<rgrid, 256>>>(x, fq, rep, out);
}

// round 5
// speedup vs baseline: 1.3500x; 1.3500x over previous
#include <cuda_runtime.h>
#include <cuda_fp16.h>
#include <cstdint>

// ============================================================================
// logits = x[2048,512] @ fq[65536,512]^T ; per-row argmax/argmin;
// out = [rep[argmax] (2048x512) | rep[argmin] (2048x512)] fp32.
//
//   1) convert x, fq to fp16
//   2) fp16 mma.sync GEMM (BK=64, 3-stage swizzled cp.async pipeline)
//      + fused per-row max/min + candidate collection
//   3) exact fp64-accum rescore of candidates + gather rep rows
// ============================================================================

#define B_ROWS 2048
#define K_ENT  65536
#define F_DIM  512

#define BM 128
#define BN 128
#define BK 64
#define NCH      (F_DIM / BK)     // 8
#define N_KTILES (K_ENT / BN)     // 512
#define N_RTILES (B_ROWS / BM)    // 16

#define STAGES  3
#define A_BYTES 16384              // 128 rows x 128B (swizzled, no pad)
#define STAGE_B 32768              // A then B
#define SMEM_TOTAL (STAGES * STAGE_B)  // 98304

#define MARGIN 0.15f
#define CAP    512

// ---------------------------------------------------------------------------
// Static device scratch
// ---------------------------------------------------------------------------
__device__ __half   g_fqh[(size_t)K_ENT * F_DIM];     // 64 MB
__device__ __half   g_xh [(size_t)B_ROWS * F_DIM];    // 2 MB
__device__ uint32_t g_mkey[2][B_ROWS];                // [0]=fkey(max), [1]=~fkey(min)
__device__ uint32_t g_ccnt[2][B_ROWS];
__device__ uint32_t g_cand[2][B_ROWS][CAP];           // 8 MB

// ---------------------------------------------------------------------------
// Helpers
// ---------------------------------------------------------------------------
__device__ __forceinline__ uint32_t smem_u32(const void* p) {
    uint32_t a;
    asm("{ .reg .u64 t; cvta.to.shared.u64 t, %1; cvt.u32.u64 %0, t; }"
        : "=r"(a) : "l"(p));
    return a;
}
__device__ __forceinline__ uint32_t fkey(float v) {
    uint32_t u = __float_as_uint(v);
    return (u & 0x80000000u) ? ~u : (u | 0x80000000u);
}
__device__ __forceinline__ float unfkey(uint32_t k) {
    uint32_t u = (k & 0x80000000u) ? (k & 0x7FFFFFFFu) : ~k;
    return __uint_as_float(u);
}
__device__ __forceinline__ void cp_async16(uint32_t sd, const void* g) {
    asm volatile("cp.async.cg.shared.global [%0], [%1], 16;"
                 :: "r"(sd), "l"(g) : "memory");
}
__device__ __forceinline__ void cp_commit() {
    asm volatile("cp.async.commit_group;" ::: "memory");
}
__device__ __forceinline__ void ldm_x4(uint32_t* r, uint32_t addr) {
    asm volatile("ldmatrix.sync.aligned.m8n8.x4.shared.b16 {%0,%1,%2,%3}, [%4];"
                 : "=r"(r[0]), "=r"(r[1]), "=r"(r[2]), "=r"(r[3]) : "r"(addr));
}
__device__ __forceinline__ void mma16816(float* c, const uint32_t* a,
                                         uint32_t b0, uint32_t b1) {
    asm volatile(
        "mma.sync.aligned.m16n8k16.row.col.f32.f16.f16.f32 "
        "{%0,%1,%2,%3}, {%4,%5,%6,%7}, {%8,%9}, {%0,%1,%2,%3};"
        : "+f"(c[0]), "+f"(c[1]), "+f"(c[2]), "+f"(c[3])
        : "r"(a[0]), "r"(a[1]), "r"(a[2]), "r"(a[3]), "r"(b0), "r"(b1));
}

// ---------------------------------------------------------------------------
// Kernel 1: fp32 -> fp16 conversion
// ---------------------------------------------------------------------------
__device__ __forceinline__ void conv4(__half* dst, const float4* __restrict__ src, int i) {
    float4 v = src[i];
    __half2* d = reinterpret_cast<__half2*>(dst);
    d[2 * (size_t)i]     = __floats2half2_rn(v.x, v.y);
    d[2 * (size_t)i + 1] = __floats2half2_rn(v.z, v.w);
}
__global__ void convert_fq_kernel(const float4* __restrict__ src, int n4) {
    int i = blockIdx.x * blockDim.x + threadIdx.x;
    if (i < n4) conv4(g_fqh, src, i);
}
__global__ void convert_x_kernel(const float4* __restrict__ src, int n4) {
    int i = blockIdx.x * blockDim.x + threadIdx.x;
    if (i < n4) conv4(g_xh, src, i);
}

// ---------------------------------------------------------------------------
// Kernel 2: reset state (deterministic across graph replays)
// ---------------------------------------------------------------------------
__global__ void init_kernel() {
    int i = blockIdx.x * blockDim.x + threadIdx.x;
    if (i < B_ROWS) {
        g_mkey[0][i] = 0u; g_mkey[1][i] = 0u;
        g_ccnt[0][i] = 0u; g_ccnt[1][i] = 0u;
    }
}

// ---------------------------------------------------------------------------
// Kernel 3: fp16 GEMM (mma.sync) + fused max/min + candidate collection
// Swizzle: byte offset o = row*128 + c16*16 -> row*128 + ((c16 ^ (row&7))<<4)
// ---------------------------------------------------------------------------
__device__ __forceinline__ void load_chunk(uint32_t sb, int stage, int c,
                                           int rowbase, int nbase, int tid) {
    const uint32_t st = sb + (uint32_t)stage * STAGE_B;
    const int cbase = c * BK;
    #pragma unroll
    for (int i = 0; i < 4; i++) {            // A: 128 rows x 64 f16 = 1024 x 16B
        const int u = tid + i * 256;
        const int row = u >> 3, c16 = u & 7;
        cp_async16(st + row * 128 + (((uint32_t)(c16 ^ (row & 7))) << 4),
                   g_xh + (size_t)(rowbase + row) * F_DIM + cbase + c16 * 8);
    }
    #pragma unroll
    for (int i = 0; i < 4; i++) {            // B: 128 n-rows x 64 f16
        const int u = tid + i * 256;
        const int row = u >> 3, c16 = u & 7;
        cp_async16(st + A_BYTES + row * 128 + (((uint32_t)(c16 ^ (row & 7))) << 4),
                   g_fqh + (size_t)(nbase + row) * F_DIM + cbase + c16 * 8);
    }
    cp_commit();
}

__global__ void __launch_bounds__(256, 2) gemm_argext_kernel() {
    extern __shared__ char smem[];
    const uint32_t sb = smem_u32(smem);
    const int tid  = threadIdx.x;
    const int lane = tid & 31;
    const int wid  = tid >> 5;
    const int wm   = wid >> 2;               // 0..1 (M)
    const int wn   = wid & 3;                // 0..3 (N)

    const int bid     = blockIdx.x;
    const int ktile   = bid >> 4;            // consecutive bids share fq slab (L2)
    const int rowtile = bid & 15;
    const int rowbase = rowtile * BM;
    const int nbase   = ktile * BN;

    float acc[4][4][4];
    #pragma unroll
    for (int a = 0; a < 4; a++)
        #pragma unroll
        for (int b = 0; b < 4; b++)
            #pragma unroll
            for (int d = 0; d < 4; d++) acc[a][b][d] = 0.0f;

    load_chunk(sb, 0, 0, rowbase, nbase, tid);
    load_chunk(sb, 1, 1, rowbase, nbase, tid);

    const int lr  = lane & 15;               // ldmatrix row within 16
    const int lc  = lane >> 4;               // ldmatrix col-half
    const uint32_t xrv = (uint32_t)(lr & 7); // swizzle xor (row field const/lane)

    for (int c = 0; c < NCH; c++) {
        asm volatile("cp.async.wait_group 1;" ::: "memory");  // chunk c landed
        __syncthreads();
        if (c + 2 < NCH) load_chunk(sb, (c + 2) % STAGES, c + 2, rowbase, nbase, tid);
        else             cp_commit();        // keep group accounting uniform

        const uint32_t a_base = sb + (uint32_t)(c % STAGES) * STAGE_B;
        const uint32_t b_base = a_base + A_BYTES;

        #pragma unroll
        for (int k16 = 0; k16 < 4; k16++) {
            const uint32_t cterm = (((uint32_t)(2 * k16) + lc) ^ xrv) << 4;
            uint32_t af[4][4], bf[2][4];
            #pragma unroll
            for (int mi = 0; mi < 4; mi++)
                ldm_x4(af[mi], a_base + (64 * wm + 16 * mi + lr) * 128 + cterm);
            #pragma unroll
            for (int nb = 0; nb < 2; nb++)
                ldm_x4(bf[nb], b_base + (32 * wn + 16 * nb + lr) * 128 + cterm);
            #pragma unroll
            for (int mi = 0; mi < 4; mi++)
                #pragma unroll
                for (int ni = 0; ni < 4; ni++) {
                    const int nb = ni >> 1, s = ni & 1;
                    mma16816(acc[mi][ni], af[mi], bf[nb][s], bf[nb][s + 2]);
                }
        }
    }

    // ---------------- epilogue: per-row max/min + candidates ----------------
    __syncthreads();                          // all async/smem use done; overlay
    uint32_t* s_maxkey = reinterpret_cast<uint32_t*>(smem);          // [128]
    uint32_t* s_minkey = s_maxkey + 128;                             // [128]
    float*    s_thr    = reinterpret_cast<float*>(s_minkey + 128);   // [256]

    if (tid < 128) { s_maxkey[tid] = 0u; s_minkey[tid] = 0u; }
    __syncthreads();

    #pragma unroll
    for (int mi = 0; mi < 4; mi++) {
        #pragma unroll
        for (int h = 0; h < 2; h++) {
            float vmax = -3.402823466e38f, vmin = 3.402823466e38f;
            #pragma unroll
            for (int ni = 0; ni < 4; ni++)
                #pragma unroll
                for (int j = 0; j < 2; j++) {
                    const float v = acc[mi][ni][2 * h + j];
                    vmax = fmaxf(vmax, v);
                    vmin = fminf(vmin, v);
                }
            #pragma unroll
            for (int off = 1; off < 4; off <<= 1) {
                vmax = fmaxf(vmax, __shfl_xor_sync(0xFFFFFFFFu, vmax, off));
                vmin = fminf(vmin, __shfl_xor_sync(0xFFFFFFFFu, vmin, off));
            }
            if ((lane & 3) == 0) {
                const int r = 64 * wm + 16 * mi + (lane >> 2) + 8 * h;
                atomicMax(&s_maxkey[r], fkey(vmax));
                atomicMax(&s_minkey[r], ~fkey(vmin));
            }
        }
    }
    __syncthreads();

    if (tid < 128) {
        const int rg = rowbase + tid;
        const float tmax = unfkey(s_maxkey[tid]);
        const uint32_t oldmax = atomicMax(&g_mkey[0][rg], s_maxkey[tid]);
        s_thr[tid] = fmaxf(unfkey(oldmax), tmax) - MARGIN;

        const float tmin = unfkey(~s_minkey[tid]);
        const uint32_t oldmin = atomicMax(&g_mkey[1][rg], s_minkey[tid]);
        s_thr[128 + tid] = fminf(unfkey(~oldmin), tmin) + MARGIN;
    }
    __syncthreads();

    #pragma unroll
    for (int mi = 0; mi < 4; mi++) {
        #pragma unroll
        for (int h = 0; h < 2; h++) {
            const int rl = 64 * wm + 16 * mi + (lane >> 2) + 8 * h;
            const float thrmax = s_thr[rl];
            const float thrmin = s_thr[128 + rl];
            const int rg = rowbase + rl;
            #pragma unroll
            for (int ni = 0; ni < 4; ni++)
                #pragma unroll
                for (int j = 0; j < 2; j++) {
                    const float v = acc[mi][ni][2 * h + j];
                    if (v >= thrmax || v <= thrmin) {
                        const uint32_t col = nbase + 32 * wn + 16 * (ni >> 1)
                                           + 8 * (ni & 1) + 2 * (lane & 3) + j;
                        if (v >= thrmax) {
                            const uint32_t p = atomicAdd(&g_ccnt[0][rg], 1u);
                            if (p < CAP) g_cand[0][rg][p] = col;
                        }
                        if (v <= thrmin) {
                            const uint32_t p = atomicAdd(&g_ccnt[1][rg], 1u);
                            if (p < CAP) g_cand[1][rg][p] = col;
                        }
                    }
                }
        }
    }
}

// ---------------------------------------------------------------------------
// Kernel 4: exact rescore (fp64 accum) + gather
// ---------------------------------------------------------------------------
__global__ void __launch_bounds__(256) rescore_kernel(
    const float* __restrict__ x, const float* __restrict__ fq,
    const float* __restrict__ rep, float* __restrict__ out) {
    const int row  = blockIdx.x;
    const int side = blockIdx.y;            // 0 = max(pos), 1 = min(neg)
    const int tid  = threadIdx.x;

    __shared__ float  sx[F_DIM];
    __shared__ double red[8];
    __shared__ uint32_t s_bidx;

    #pragma unroll
    for (int i = tid; i < F_DIM; i += 256) sx[i] = x[(size_t)row * F_DIM + i];
    __syncthreads();

    uint32_t cnt = g_ccnt[side][row];
    if (cnt > CAP) cnt = CAP;

    double  bestv = side ? 1.0e300 : -1.0e300;
    uint32_t bidx = 0xFFFFFFFFu;

    for (uint32_t i = 0; i < cnt; i++) {
        const uint32_t idx = g_cand[side][row][i];
        const float* fr = fq + (size_t)idx * F_DIM;
        double p = 0.0;
        #pragma unroll
        for (int j = tid; j < F_DIM; j += 256)
            p += (double)sx[j] * (double)fr[j];
        #pragma unroll
        for (int off = 16; off > 0; off >>= 1)
            p += __shfl_xor_sync(0xFFFFFFFFu, p, off);
        if ((tid & 31) == 0) red[tid >> 5] = p;
        __syncthreads();
        if (tid == 0) {
            double d = 0.0;
            #pragma unroll
            for (int w = 0; w < 8; w++) d += red[w];
            const bool better = side ? (d < bestv || (d == bestv && idx < bidx))
                                     : (d > bestv || (d == bestv && idx < bidx));
            if (better) { bestv = d; bidx = idx; }
        }
        __syncthreads();
    }
    if (tid == 0) s_bidx = bidx;
    __syncthreads();

    const float2* src = reinterpret_cast<const float2*>(rep + (size_t)s_bidx * F_DIM);
    float2* dst = reinterpret_cast<float2*>(
        out + (size_t)side * B_ROWS * F_DIM + (size_t)row * F_DIM);
    dst[tid] = src[tid];                    // 256 threads x 8B = 512 floats
}

// ---------------------------------------------------------------------------
// Entry point
// ---------------------------------------------------------------------------
extern "C" void kernel_launch(void* const* d_in, const int* in_sizes, int n_in,
                              void* d_out, int out_size) {
    const float* x   = (const float*)d_in[0];  // [2048, 512]
    const float* fq  = (const float*)d_in[1];  // [65536, 512]
    const float* rep = (const float*)d_in[2];  // [65536, 512]
    float* out = (float*)d_out;                // [2, 2048, 512]

    cudaFuncSetAttribute(gemm_argext_kernel,
                         cudaFuncAttributeMaxDynamicSharedMemorySize, SMEM_TOTAL);

    {
        const int n4 = (K_ENT * F_DIM) / 4;
        convert_fq_kernel<<<n4 / 256, 256>>>(reinterpret_cast<const float4*>(fq), n4);
    }
    {
        const int n4 = (B_ROWS * F_DIM) / 4;
        convert_x_kernel<<<n4 / 256, 256>>>(reinterpret_cast<const float4*>(x), n4);
    }
    init_kernel<<<(B_ROWS + 255) / 256, 256>>>();

    gemm_argext_kernel<<<N_KTILES * N_RTILES, 256, SMEM_TOTAL>>>();

    dim3 rgrid(B_ROWS, 2);
    rescore_kernel<<<rgrid, 256>>>(x, fq, rep, out);
}